// round 2
// baseline (speedup 1.0000x reference)
#include <cuda_runtime.h>
#include <cuda_bf16.h>
#include <math.h>

// ---------------- problem constants ----------------
#define NN_ 200      // nodes
#define UU  64       // rnn units
#define BB  64       // batch
#define TT  12       // T_IN == T_OUT
#define LL  4
#define ROWS (NN_*BB)        // 12800
#define FMAX 264             // layer0: 200+64
#define CHUNK (ROWS*FMAX)    // 3,379,200 floats per chebyshev term

// ---------------- device scratch (static: no runtime allocs) ----------------
__device__ float g_X[3*CHUNK];      // [x0|x1|x2] for gate gconv
__device__ float g_C[3*CHUNK];      // [c0|c1|c2] for candidate gconv
__device__ float g_RH[ROWS*UU];     // r * h
__device__ float g_U [ROWS*UU];     // update gate u
__device__ float g_H [LL*ROWS*UU];  // hidden states, (N,B,U) rows = n*B+b
__device__ float g_PROJ[BB*NN_*NN_];// previous decoder projection (B, N*N)
__device__ float g_Wg_e[792*128 + 3*384*128];
__device__ float g_Wg_d[792*128 + 3*384*128];
__device__ float g_Wc_e[792*64  + 3*384*64];
__device__ float g_Wc_d[792*64  + 3*384*64];

// ---------------- small kernels ----------------
__global__ void zerok(float* p, int n) {
    int i = blockIdx.x * 256 + threadIdx.x;
    if (i < n) p[i] = 0.f;
}

// repack weights: src rows are (f*3 + k), dst rows are (k*F + f)
__global__ void wprep(const float* __restrict__ src, float* __restrict__ dst,
                      int F, int out) {
    int idx = blockIdx.x * 256 + threadIdx.x;
    int total = 3 * F * out;
    if (idx >= total) return;
    int c = idx % out;
    int r = idx / out;        // dst row = k*F + f
    int k = r / F;
    int f = r - k * F;
    dst[idx] = src[(f * 3 + k) * out + c];
}

// build concatenated per-node features: dst row (n,b) = [x(Fi) | state(64)]
// xmode: 0 = encoder input (transpose from inputs), 1 = g_PROJ, 2 = zeros,
//        3 = previous layer hidden (N,B,64), 4 = copy x-part from g_X[0]
__global__ void build_cat(float* __restrict__ dst,
                          const float* __restrict__ xsrc, int xmode, int t,
                          const float* __restrict__ st, int Fi) {
    int F = Fi + UU;
    int idx = blockIdx.x * 256 + threadIdx.x;
    int total = ROWS * F;
    if (idx >= total) return;
    int row = idx / F;
    int f = idx - row * F;
    int n = row >> 6, b = row & 63;
    float v;
    if (f < Fi) {
        if (xmode == 0)      v = xsrc[((long)b * TT + t) * 40000 + (long)n * 200 + f];
        else if (xmode == 1) v = xsrc[(long)b * 40000 + (long)n * 200 + f];
        else if (xmode == 2) v = 0.f;
        else if (xmode == 3) v = xsrc[row * UU + f];
        else                 v = xsrc[(long)row * F + f];
    } else {
        v = st[row * UU + (f - Fi)];
    }
    dst[(long)row * F + f] = v;
}

// ---------------- generic SGEMM with fused epilogues ----------------
// C(M,Nn) = A(M,K) @ B(K,Nn), all row-major.
// Fblk>0: A is 3 equally spaced chunks (stride ablk), each rows with ld=Fblk.
// MODE: 0 plain, 1 cheb (2*acc - X0), 2 gates (sigmoid -> RH,U),
//       3 cand (tanh -> GRU update in-place), 4 projection (+dual store)
#define BM 128
#define BN 64
#define BK 8

template<int MODE>
__global__ __launch_bounds__(256) void gemm_k(
    const float* __restrict__ A, int lda, int Fblk, long ablk,
    const float* __restrict__ Bm, int ldb,
    float* __restrict__ Cm, int ldc,
    int M, int Nn, int K,
    const float* __restrict__ bias,
    const float* __restrict__ X0, int ldx0,
    const float* __restrict__ H,
    float* __restrict__ O1,
    float* __restrict__ O2,
    const float* __restrict__ Uin,
    float* __restrict__ out2, int t)
{
    __shared__ float As[BK][BM];
    __shared__ float Bs[BK][BN];
    int tid = threadIdx.x;
    int tx = tid & 15, ty = tid >> 4;
    int m0 = blockIdx.y * BM, n0 = blockIdx.x * BN;

    float acc[8][4];
#pragma unroll
    for (int i = 0; i < 8; i++)
#pragma unroll
        for (int j = 0; j < 4; j++) acc[i][j] = 0.f;

    int la_m = tid >> 2;             // 0..63
    int la_k = (tid & 3) * 2;        // 0,2,4,6
    int lb_r = tid >> 5;             // 0..7
    int lb_c = (tid & 31) * 2;       // 0..62

    for (int k0 = 0; k0 < K; k0 += BK) {
        const float* Ab = A;
        int krel = k0;
        if (Fblk) {
            int kb = k0 / Fblk;
            Ab = A + (long)kb * ablk;
            krel = k0 - kb * Fblk;
        }
#pragma unroll
        for (int mm = 0; mm < 2; mm++) {
            int m = la_m + mm * 64;
            float x = 0.f, y = 0.f;
            int gm = m0 + m;
            if (gm < M) {
                const float* p = Ab + (long)gm * lda + krel + la_k;
                x = p[0]; y = p[1];
            }
            As[la_k][m] = x;
            As[la_k + 1][m] = y;
        }
        {
            float x = 0.f, y = 0.f;
            int gn = n0 + lb_c;
            if (gn < Nn) {
                const float* p = Bm + (long)(k0 + lb_r) * ldb + gn;
                x = p[0]; y = p[1];
            }
            Bs[lb_r][lb_c] = x;
            Bs[lb_r][lb_c + 1] = y;
        }
        __syncthreads();
#pragma unroll
        for (int kk = 0; kk < BK; kk++) {
            float a[8], bb[4];
#pragma unroll
            for (int i = 0; i < 8; i++) a[i] = As[kk][ty * 8 + i];
#pragma unroll
            for (int j = 0; j < 4; j++) bb[j] = Bs[kk][tx * 4 + j];
#pragma unroll
            for (int i = 0; i < 8; i++)
#pragma unroll
                for (int j = 0; j < 4; j++) acc[i][j] += a[i] * bb[j];
        }
        __syncthreads();
    }

#pragma unroll
    for (int i = 0; i < 8; i++) {
        int gm = m0 + ty * 8 + i;
        if (gm >= M) continue;
#pragma unroll
        for (int j = 0; j < 4; j++) {
            int gn = n0 + tx * 4 + j;
            if (gn >= Nn) continue;
            float v = acc[i][j];
            if (MODE == 0) {
                Cm[(long)gm * ldc + gn] = v;
            } else if (MODE == 1) {
                Cm[(long)gm * ldc + gn] = 2.f * v - X0[(long)gm * ldx0 + gn];
            } else if (MODE == 2) {
                float s = 1.f / (1.f + expf(-(v + bias[gn])));
                if (gn < UU) O1[gm * UU + gn] = s * H[gm * UU + gn];  // r*h
                else         O2[gm * UU + gn - UU] = s;               // u
            } else if (MODE == 3) {
                float c = tanhf(v + bias[gn]);
                float u = Uin[gm * UU + gn];
                O1[gm * UU + gn] = u * H[gm * UU + gn] + (1.f - u) * c;
            } else {  // MODE == 4 projection
                float p = v + bias[gn];
                int b_ = gm & 63, n_ = gm >> 6;
                Cm[((long)b_ * TT + t) * 40000 + (long)n_ * 200 + gn] = p;
                out2[(long)b_ * 40000 + (long)n_ * 200 + gn] = p;
            }
        }
    }
}

// ---------------- host orchestration ----------------
extern "C" void kernel_launch(void* const* d_in, const int* in_sizes, int n_in,
                              void* d_out, int out_size) {
    (void)in_sizes; (void)n_in; (void)out_size;
    const float* inputs  = (const float*)d_in[0];
    const float* Ssup    = (const float*)d_in[1];
    const float* enc_Wg0 = (const float*)d_in[2];
    const float* enc_bg0 = (const float*)d_in[3];
    const float* enc_Wc0 = (const float*)d_in[4];
    const float* enc_bc0 = (const float*)d_in[5];
    const float* enc_Wg  = (const float*)d_in[6];
    const float* enc_bg  = (const float*)d_in[7];
    const float* enc_Wc  = (const float*)d_in[8];
    const float* enc_bc  = (const float*)d_in[9];
    const float* dec_Wg0 = (const float*)d_in[10];
    const float* dec_bg0 = (const float*)d_in[11];
    const float* dec_Wc0 = (const float*)d_in[12];
    const float* dec_bc0 = (const float*)d_in[13];
    const float* dec_Wg  = (const float*)d_in[14];
    const float* dec_bg  = (const float*)d_in[15];
    const float* dec_Wc  = (const float*)d_in[16];
    const float* dec_bc  = (const float*)d_in[17];
    const float* proj_W  = (const float*)d_in[18];
    const float* proj_b  = (const float*)d_in[19];
    float* out = (float*)d_out;

    float *pX, *pC, *pRH, *pU, *pH, *pPROJ, *pWge, *pWgd, *pWce, *pWcd;
    cudaGetSymbolAddress((void**)&pX,    g_X);
    cudaGetSymbolAddress((void**)&pC,    g_C);
    cudaGetSymbolAddress((void**)&pRH,   g_RH);
    cudaGetSymbolAddress((void**)&pU,    g_U);
    cudaGetSymbolAddress((void**)&pH,    g_H);
    cudaGetSymbolAddress((void**)&pPROJ, g_PROJ);
    cudaGetSymbolAddress((void**)&pWge,  g_Wg_e);
    cudaGetSymbolAddress((void**)&pWgd,  g_Wg_d);
    cudaGetSymbolAddress((void**)&pWce,  g_Wc_e);
    cudaGetSymbolAddress((void**)&pWcd,  g_Wc_d);

    // ---- weight repack (runs every call; cheap, deterministic) ----
    // gate weights: layer0 F=264 out=128, layers 1..3 F=128 out=128
    wprep<<<(3*264*128)/256, 256>>>(enc_Wg0, pWge, 264, 128);
    wprep<<<(3*264*128)/256, 256>>>(dec_Wg0, pWgd, 264, 128);
    for (int i = 0; i < 3; i++) {
        wprep<<<(3*128*128)/256, 256>>>(enc_Wg + (long)i*384*128,
                                        pWge + 792*128 + (long)i*384*128, 128, 128);
        wprep<<<(3*128*128)/256, 256>>>(dec_Wg + (long)i*384*128,
                                        pWgd + 792*128 + (long)i*384*128, 128, 128);
    }
    wprep<<<(3*264*64)/256, 256>>>(enc_Wc0, pWce, 264, 64);
    wprep<<<(3*264*64)/256, 256>>>(dec_Wc0, pWcd, 264, 64);
    for (int i = 0; i < 3; i++) {
        wprep<<<(3*128*64)/256, 256>>>(enc_Wc + (long)i*384*64,
                                       pWce + 792*64 + (long)i*384*64, 128, 64);
        wprep<<<(3*128*64)/256, 256>>>(dec_Wc + (long)i*384*64,
                                       pWcd + 792*64 + (long)i*384*64, 128, 64);
    }

    // ---- zero initial hidden state ----
    zerok<<<(LL*ROWS*UU)/256, 256>>>(pH, LL*ROWS*UU);

    // ---- sequence loop ----
    for (int tg = 0; tg < 2 * TT; tg++) {
        bool enc = (tg < TT);
        int t = enc ? tg : (tg - TT);
        const float* Wgside = enc ? pWge : pWgd;
        const float* Wcside = enc ? pWce : pWcd;

        for (int l = 0; l < LL; l++) {
            int Fi = (l == 0) ? 200 : 64;
            int F = Fi + UU;
            int BF = BB * F;
            float* hl = pH + (long)l * ROWS * UU;

            const float* Wg = (l == 0) ? Wgside : Wgside + 792*128 + (long)(l-1)*384*128;
            const float* Wc = (l == 0) ? Wcside : Wcside + 792*64  + (long)(l-1)*384*64;
            const float* bg = enc ? ((l == 0) ? enc_bg0 : enc_bg + (l-1)*128)
                                  : ((l == 0) ? dec_bg0 : dec_bg + (l-1)*128);
            const float* bc = enc ? ((l == 0) ? enc_bc0 : enc_bc + (l-1)*64)
                                  : ((l == 0) ? dec_bc0 : dec_bc + (l-1)*64);

            int xmode;
            const float* xsrc;
            if (l > 0)      { xmode = 3; xsrc = pH + (long)(l-1) * ROWS * UU; }
            else if (enc)   { xmode = 0; xsrc = inputs; }
            else if (t == 0){ xmode = 2; xsrc = pPROJ; }
            else            { xmode = 1; xsrc = pPROJ; }

            // X0 = [x | h]
            build_cat<<<(ROWS*F)/256, 256>>>(pX, xsrc, xmode, t, hl, Fi);
            // X1 = S @ X0
            gemm_k<0><<<dim3(BF/64, 2), 256>>>(Ssup, 200, 0, 0, pX, BF,
                pX + CHUNK, BF, 200, BF, 200,
                nullptr, nullptr, 0, nullptr, nullptr, nullptr, nullptr, nullptr, 0);
            // X2 = 2*S@X1 - X0
            gemm_k<1><<<dim3(BF/64, 2), 256>>>(Ssup, 200, 0, 0, pX + CHUNK, BF,
                pX + 2*CHUNK, BF, 200, BF, 200,
                nullptr, pX, BF, nullptr, nullptr, nullptr, nullptr, nullptr, 0);
            // gates = sigmoid([X0|X1|X2] @ Wg + bg) -> RH = r*h, U = u
            gemm_k<2><<<dim3(2, 100), 256>>>(pX, F, F, (long)CHUNK, Wg, 128,
                nullptr, 0, ROWS, 128, 3*F,
                bg, nullptr, 0, hl, pRH, pU, nullptr, nullptr, 0);
            // C0 = [x | r*h]
            build_cat<<<(ROWS*F)/256, 256>>>(pC, pX, 4, t, pRH, Fi);
            // C1 = S @ C0
            gemm_k<0><<<dim3(BF/64, 2), 256>>>(Ssup, 200, 0, 0, pC, BF,
                pC + CHUNK, BF, 200, BF, 200,
                nullptr, nullptr, 0, nullptr, nullptr, nullptr, nullptr, nullptr, 0);
            // C2 = 2*S@C1 - C0
            gemm_k<1><<<dim3(BF/64, 2), 256>>>(Ssup, 200, 0, 0, pC + CHUNK, BF,
                pC + 2*CHUNK, BF, 200, BF, 200,
                nullptr, pC, BF, nullptr, nullptr, nullptr, nullptr, nullptr, 0);
            // c = tanh([C0|C1|C2] @ Wc + bc); h = u*h + (1-u)*c (in place)
            gemm_k<3><<<dim3(1, 100), 256>>>(pC, F, F, (long)CHUNK, Wc, 64,
                nullptr, 0, ROWS, 64, 3*F,
                bc, nullptr, 0, hl, hl, nullptr, pU, nullptr, 0);
        }

        if (!enc) {
            // projection: out[b,t,:] and next decoder input
            gemm_k<4><<<dim3(4, 100), 256>>>(pH + (long)3 * ROWS * UU, UU, 0, 0,
                proj_W, 200, out, 0, ROWS, 200, UU,
                proj_b, nullptr, 0, nullptr, nullptr, nullptr, nullptr, pPROJ, t);
        }
    }
}